// round 8
// baseline (speedup 1.0000x reference)
#include <cuda_runtime.h>
#include <cstdint>
#include <math.h>

#define BB   4
#define SS   2048
#define EE   1024
#define HH   16
#define DKK  64
#define MTOT (BB*SS)   // 8192

// Scratch (device globals; no allocation allowed)
__device__ float g_X[(size_t)MTOT*EE];            // tf32-rounded X
__device__ float g_Q[(size_t)BB*HH*SS*DKK];       // rounded at write
__device__ float g_K[(size_t)BB*HH*SS*DKK];
__device__ float g_V[(size_t)BB*HH*SS*DKK];
__device__ float g_A[(size_t)MTOT*EE];            // rounded at write
__device__ float g_WT[(size_t)4*EE*EE];           // transposed + rounded weights

// ===========================================================================
// helpers
// ===========================================================================

__device__ __forceinline__ uint32_t f2tf(float v) {
    uint32_t u;
    asm("cvt.rna.tf32.f32 %0, %1;" : "=r"(u) : "f"(v));
    return u;
}
__device__ __forceinline__ float f2tff(float v) {
    return __uint_as_float(f2tf(v));
}

__device__ __forceinline__ void mma_tf32(float* c, const uint32_t* a, const uint32_t* b) {
    asm volatile(
        "mma.sync.aligned.m16n8k8.row.col.f32.tf32.tf32.f32 "
        "{%0,%1,%2,%3}, {%4,%5,%6,%7}, {%8,%9}, {%0,%1,%2,%3};"
        : "+f"(c[0]), "+f"(c[1]), "+f"(c[2]), "+f"(c[3])
        : "r"(a[0]), "r"(a[1]), "r"(a[2]), "r"(a[3]), "r"(b[0]), "r"(b[1]));
}

__device__ __forceinline__ void ldsm_x4(uint32_t* r, uint32_t addr) {
    asm volatile("ldmatrix.sync.aligned.m8n8.x4.shared.b16 {%0,%1,%2,%3}, [%4];"
                 : "=r"(r[0]), "=r"(r[1]), "=r"(r[2]), "=r"(r[3]) : "r"(addr));
}

__device__ __forceinline__ uint32_t smem_u32(const void* p) {
    uint32_t a;
    asm("{ .reg .u64 t; cvta.to.shared.u64 t, %1; cvt.u32.u64 %0, t; }"
        : "=r"(a) : "l"(p));
    return a;
}

__device__ __forceinline__ void cp16(uint32_t dst, const float* src) {
    asm volatile("cp.async.cg.shared.global [%0], [%1], 16;"
                 :: "r"(dst), "l"(src) : "memory");
}
#define CP_COMMIT() asm volatile("cp.async.commit_group;" ::: "memory")
#define CP_WAIT(N)  asm volatile("cp.async.wait_group %0;" :: "n"(N) : "memory")

// ===========================================================================
// Prepass: round X to tf32.
// ===========================================================================
__global__ __launch_bounds__(256) void xround_kernel(const float* __restrict__ X)
{
    size_t i = ((size_t)blockIdx.x * 256 + threadIdx.x) * 4;
    float4 v = *(const float4*)(X + i);
    *(float4*)(g_X + i) = make_float4(f2tff(v.x), f2tff(v.y), f2tff(v.z), f2tff(v.w));
}

// Weight transpose + round: g_WT[w][n][k] = rna(W_w[k][n])
__global__ __launch_bounds__(256) void wtrans_kernel(
    const float* __restrict__ WQ, const float* __restrict__ WK,
    const float* __restrict__ WV, const float* __restrict__ WO)
{
    __shared__ float t[32][33];
    const int w = blockIdx.z;
    const float* W = (w == 0) ? WQ : (w == 1) ? WK : (w == 2) ? WV : WO;
    float* O = g_WT + (size_t)w * EE * EE;
    const int n0 = blockIdx.x * 32;
    const int k0 = blockIdx.y * 32;
    const int tx = threadIdx.x, ty = threadIdx.y;

#pragma unroll
    for (int i = ty; i < 32; i += 8)
        t[i][tx] = W[(size_t)(k0 + i) * EE + n0 + tx];
    __syncthreads();
#pragma unroll
    for (int i = ty; i < 32; i += 8)
        O[(size_t)(n0 + i) * EE + k0 + tx] = f2tff(t[tx][i]);
}

// ===========================================================================
// tf32 GEMM (unchanged): 128x128 tile, 256 thr, cp.async 3-stage, ldmatrix.
// ===========================================================================
#define GSTAGE  36864
#define GEMM_SMEM_BYTES (3 * GSTAGE)        // 110592

template <int MODE>
__global__ __launch_bounds__(256, 2) void gemm_tc(float* __restrict__ OutP)
{
    extern __shared__ float smf[];
    const uint32_t sb = smem_u32(smf);
    const int tid  = threadIdx.x;
    const int lane = tid & 31;
    const int w    = tid >> 5;
    const int g    = lane >> 2;
    const int tg   = lane & 3;
    const int wm   = w & 3;
    const int wn   = w >> 2;
    const int m0   = blockIdx.y * 128;
    const int n0   = blockIdx.x * 128;

    const float* Ag = MODE ? g_A : g_X;
    const float* Bt = g_WT + (size_t)(MODE ? 3 : blockIdx.z) * EE * EE;
    float* outp;
    if (MODE) outp = OutP;
    else outp = (blockIdx.z == 0) ? g_Q : (blockIdx.z == 1) ? g_K : g_V;

    const int cr = tid >> 3;
    const int cc = tid & 7;

    const uint32_t aoff = (uint32_t)(lane & 15) * 144u + ((lane >> 4) & 1) * 16u;
    const uint32_t boff = (uint32_t)((lane & 7) + ((lane & 16) >> 1)) * 144u
                        + ((lane & 8) >> 3) * 16u;

    auto issue = [&](int s) {
        const uint32_t ab = sb + (uint32_t)(s % 3) * GSTAGE;
        const uint32_t bb = ab + 18432u;
        const int k0 = s * 32;
#pragma unroll
        for (int i = 0; i < 4; i++) {
            int r = cr + i * 32;
            cp16(ab + (uint32_t)r * 144u + cc * 16u,
                 Ag + (size_t)(m0 + r) * EE + k0 + cc * 4);
            cp16(bb + (uint32_t)r * 144u + cc * 16u,
                 Bt + (size_t)(n0 + r) * EE + k0 + cc * 4);
        }
    };

    float c[2][8][4];
#pragma unroll
    for (int mt = 0; mt < 2; mt++)
#pragma unroll
        for (int nt = 0; nt < 8; nt++)
#pragma unroll
            for (int i = 0; i < 4; i++) c[mt][nt][i] = 0.f;

    issue(0); CP_COMMIT();
    issue(1); CP_COMMIT();

    for (int j = 0; j < 32; j++) {
        __syncthreads();
        if (j + 2 < 32) issue(j + 2);
        CP_COMMIT();
        CP_WAIT(2);
        __syncthreads();

        const uint32_t ab = sb + (uint32_t)(j % 3) * GSTAGE;
        const uint32_t bb = ab + 18432u;
#pragma unroll
        for (int ks = 0; ks < 4; ks++) {
            uint32_t a[2][4], bq[4][4];
            ldsm_x4(a[0], ab + (uint32_t)(wm * 32     ) * 144u + ks * 32u + aoff);
            ldsm_x4(a[1], ab + (uint32_t)(wm * 32 + 16) * 144u + ks * 32u + aoff);
#pragma unroll
            for (int p = 0; p < 4; p++)
                ldsm_x4(bq[p], bb + (uint32_t)(wn * 64 + p * 16) * 144u + ks * 32u + boff);
#pragma unroll
            for (int mt = 0; mt < 2; mt++)
#pragma unroll
                for (int nt = 0; nt < 8; nt++)
                    mma_tf32(c[mt][nt], a[mt], &bq[nt >> 1][(nt & 1) * 2]);
        }
    }

#pragma unroll
    for (int mt = 0; mt < 2; mt++) {
#pragma unroll
        for (int nt = 0; nt < 8; nt++) {
            int row = m0 + wm * 32 + mt * 16 + g;
            int col = n0 + wn * 64 + nt * 8 + 2 * tg;
            if (MODE) {
                float* o0 = outp + (size_t)row * EE + col;
                float* o1 = outp + (size_t)(row + 8) * EE + col;
                *(float2*)o0 = make_float2(c[mt][nt][0], c[mt][nt][1]);
                *(float2*)o1 = make_float2(c[mt][nt][2], c[mt][nt][3]);
            } else {
                int bidx = row >> 11;
                int s    = row & (SS - 1);
                int h    = col >> 6;
                int d    = col & 63;
                float* o0 = outp + (((size_t)(bidx * HH + h) * SS + s    ) * DKK + d);
                float* o1 = outp + (((size_t)(bidx * HH + h) * SS + s + 8) * DKK + d);
                *(float2*)o0 = make_float2(f2tff(c[mt][nt][0]), f2tff(c[mt][nt][1]));
                *(float2*)o1 = make_float2(f2tff(c[mt][nt][2]), f2tff(c[mt][nt][3]));
            }
        }
    }
}

// ===========================================================================
// Causal flash attention v5: CTA = 128 q-rows, 8 warps (256 thr), 2 CTAs/SM.
// K single-buffered (cp.async, issued post-QK, covered by softmax+PV);
// V LDG at loop top (covered by QK) -> transposed STS -> ldmatrix PV.
// SMEM = 102KB -> two co-resident CTAs overlap softmax with MMA.
// ===========================================================================
#define AST 68
#define ASTB 272u
#define AKV (64 * AST)
#define AQROWS 128
#define ATTN_SMEM_FLOATS (AQROWS*AST + AKV + AKV + AQROWS*AST)
#define ATTN_SMEM_BYTES  (ATTN_SMEM_FLOATS * 4)   // 104448

__global__ __launch_bounds__(256, 2) void attn_tc()
{
    extern __shared__ float sm[];
    float* Qs = sm;                          // [128][68]
    float* Vt = sm + AQROWS * AST + AKV;     // [64][68]  Vt[d][t]
    float* Ps = Vt + AKV;                    // [128][68]
    const uint32_t sb   = smem_u32(sm);
    const uint32_t Qb   = sb;
    const uint32_t Kb   = sb + AQROWS * ASTB;           // single K buffer
    const uint32_t Vtb  = Kb + 64 * ASTB;
    const uint32_t Pb   = Vtb + 64 * ASTB;

    const int tid  = threadIdx.x;
    const int lane = tid & 31;
    const int w    = tid >> 5;               // 0..7
    const int g    = lane >> 2;
    const int tg   = lane & 3;

    const int qblk = gridDim.x - 1 - blockIdx.x;   // heavy CTAs first
    const int q0   = qblk * AQROWS;
    const int h    = blockIdx.y;
    const int b    = blockIdx.z;
    const size_t base = ((size_t)(b * HH + h) * SS) * DKK;

    const uint32_t aoff = (uint32_t)(lane & 15) * ASTB + ((lane >> 4) & 1) * 16u;
    const uint32_t boff = (uint32_t)((lane & 7) + ((lane & 16) >> 1)) * ASTB
                        + ((lane & 8) >> 3) * 16u;

    // cp.async K mapping (64x64 tile, 256 threads -> 4 segs each).
    const int cr = tid >> 2;                  // 0..63 (row)
    const int cc4 = tid & 3;                  // seg group; c = cc4 + 4*i

    // V transpose mapping: thread covers V[vt][vd0..vd0+15].
    const int vt  = tid & 63;
    const int vd0 = (tid >> 6) << 4;          // 0,16,32,48

    auto issue_K = [&](int j) {
        const int t0 = j * 64;
#pragma unroll
        for (int i = 0; i < 4; i++) {
            int c = cc4 * 4 + i;               // 0..15
            cp16(Kb + (uint32_t)cr * ASTB + (uint32_t)c * 16u,
                 g_K + base + (size_t)(t0 + cr) * DKK + c * 4);
        }
    };

    // Prologue: K[0] inbound; stage Q (pre-rounded), 128x64.
    issue_K(0); CP_COMMIT();
#pragma unroll
    for (int i = 0; i < 8; i++) {
        int f = tid + i * 256;
        int r = f >> 4, c4 = f & 15;
        float4 v = *(const float4*)(g_Q + base + (size_t)(q0 + r) * DKK + c4 * 4);
        *(float4*)(Qs + r * AST + c4 * 4) = v;
    }

    float o[8][4];
#pragma unroll
    for (int nt = 0; nt < 8; nt++)
#pragma unroll
        for (int i = 0; i < 4; i++) o[nt][i] = 0.f;
    float m0 = -1e30f, m1 = -1e30f, l0 = 0.f, l1 = 0.f;

    const int nch   = 2 * qblk + 2;
    const int rbase = w * 16;
    const int grow0 = q0 + rbase + g;

    for (int j = 0; j < nch; j++) {
        CP_WAIT(0);                      // K[j] landed
        __syncthreads();                 // sync1: K visible; PV[j-1] done (Vt free)

        const int t0 = j * 64;
        // V_j global loads (consumed at STS after QK).
        float4 rv0 = *(const float4*)(g_V + base + (size_t)(t0 + vt) * DKK + vd0);
        float4 rv1 = *(const float4*)(g_V + base + (size_t)(t0 + vt) * DKK + vd0 + 4);
        float4 rv2 = *(const float4*)(g_V + base + (size_t)(t0 + vt) * DKK + vd0 + 8);
        float4 rv3 = *(const float4*)(g_V + base + (size_t)(t0 + vt) * DKK + vd0 + 12);

        const bool active = (t0 <= q0 + rbase + 15);
        float s[8][4];

        if (active) {
            // ---- S = Q K^T ----
#pragma unroll
            for (int nt = 0; nt < 8; nt++)
#pragma unroll
                for (int i = 0; i < 4; i++) s[nt][i] = 0.f;

#pragma unroll
            for (int ks = 0; ks < 8; ks++) {
                uint32_t a[4], bq[4][4];
                ldsm_x4(a, Qb + (uint32_t)rbase * ASTB + ks * 32u + aoff);
#pragma unroll
                for (int p = 0; p < 4; p++)
                    ldsm_x4(bq[p], Kb + (uint32_t)(p * 16) * ASTB + ks * 32u + boff);
#pragma unroll
                for (int nt = 0; nt < 8; nt++)
                    mma_tf32(s[nt], a, &bq[nt >> 1][(nt & 1) * 2]);
            }
        }
        __syncthreads();                 // sync2: QK reads done -> K buffer free

        // ---- V transpose STS (Vt free since sync1; regs die here) ----
        {
            float* col = Vt + vt;
            col[(vd0 + 0) * AST] = rv0.x;  col[(vd0 + 1) * AST] = rv0.y;
            col[(vd0 + 2) * AST] = rv0.z;  col[(vd0 + 3) * AST] = rv0.w;
            col[(vd0 + 4) * AST] = rv1.x;  col[(vd0 + 5) * AST] = rv1.y;
            col[(vd0 + 6) * AST] = rv1.z;  col[(vd0 + 7) * AST] = rv1.w;
            col[(vd0 + 8) * AST] = rv2.x;  col[(vd0 + 9) * AST] = rv2.y;
            col[(vd0 +10) * AST] = rv2.z;  col[(vd0 +11) * AST] = rv2.w;
            col[(vd0 +12) * AST] = rv3.x;  col[(vd0 +13) * AST] = rv3.y;
            col[(vd0 +14) * AST] = rv3.z;  col[(vd0 +15) * AST] = rv3.w;
        }
        // ---- kick K[j+1] into the (now free) single buffer ----
        if (j + 1 < nch) { issue_K(j + 1); CP_COMMIT(); }

        if (active) {
            // ---- scale + causal mask ----
#pragma unroll
            for (int nt = 0; nt < 8; nt++) {
                int c0 = t0 + nt * 8 + 2 * tg;
                int c1 = c0 + 1;
                s[nt][0] = (c0 <= grow0    ) ? s[nt][0] * 0.125f : -1e30f;
                s[nt][1] = (c1 <= grow0    ) ? s[nt][1] * 0.125f : -1e30f;
                s[nt][2] = (c0 <= grow0 + 8) ? s[nt][2] * 0.125f : -1e30f;
                s[nt][3] = (c1 <= grow0 + 8) ? s[nt][3] * 0.125f : -1e30f;
            }

            // ---- online softmax ----
            float mx0 = -1e30f, mx1 = -1e30f;
#pragma unroll
            for (int nt = 0; nt < 8; nt++) {
                mx0 = fmaxf(mx0, fmaxf(s[nt][0], s[nt][1]));
                mx1 = fmaxf(mx1, fmaxf(s[nt][2], s[nt][3]));
            }
            mx0 = fmaxf(mx0, __shfl_xor_sync(0xffffffffu, mx0, 1));
            mx0 = fmaxf(mx0, __shfl_xor_sync(0xffffffffu, mx0, 2));
            mx1 = fmaxf(mx1, __shfl_xor_sync(0xffffffffu, mx1, 1));
            mx1 = fmaxf(mx1, __shfl_xor_sync(0xffffffffu, mx1, 2));
            float mn0 = fmaxf(m0, mx0), mn1 = fmaxf(m1, mx1);
            float sc0 = __expf(m0 - mn0), sc1 = __expf(m1 - mn1);

            float rs0 = 0.f, rs1 = 0.f;
#pragma unroll
            for (int nt = 0; nt < 8; nt++) {
                float p0 = f2tff(__expf(s[nt][0] - mn0));
                float p1 = f2tff(__expf(s[nt][1] - mn0));
                float p2 = f2tff(__expf(s[nt][2] - mn1));
                float p3 = f2tff(__expf(s[nt][3] - mn1));
                rs0 += p0 + p1;
                rs1 += p2 + p3;
                *(float2*)&Ps[(rbase + g    ) * AST + nt * 8 + 2 * tg] = make_float2(p0, p1);
                *(float2*)&Ps[(rbase + g + 8) * AST + nt * 8 + 2 * tg] = make_float2(p2, p3);
            }
            rs0 += __shfl_xor_sync(0xffffffffu, rs0, 1);
            rs0 += __shfl_xor_sync(0xffffffffu, rs0, 2);
            rs1 += __shfl_xor_sync(0xffffffffu, rs1, 1);
            rs1 += __shfl_xor_sync(0xffffffffu, rs1, 2);
            l0 = l0 * sc0 + rs0;
            l1 = l1 * sc1 + rs1;
            m0 = mn0; m1 = mn1;
#pragma unroll
            for (int nt = 0; nt < 8; nt++) {
                o[nt][0] *= sc0; o[nt][1] *= sc0;
                o[nt][2] *= sc1; o[nt][3] *= sc1;
            }
        }
        __syncthreads();                 // sync3: Vt ready for all warps

        if (active) {
            // ---- O += P V (B-fragments via ldmatrix from Vt) ----
#pragma unroll
            for (int ks = 0; ks < 8; ks++) {
                uint32_t a[4], bv[4][4];
                ldsm_x4(a, Pb + (uint32_t)rbase * ASTB + ks * 32u + aoff);
#pragma unroll
                for (int p = 0; p < 4; p++)
                    ldsm_x4(bv[p], Vtb + (uint32_t)(p * 16) * ASTB + ks * 32u + boff);
#pragma unroll
                for (int nt = 0; nt < 8; nt++)
                    mma_tf32(o[nt], a, &bv[nt >> 1][(nt & 1) * 2]);
            }
        }
    }

    // Epilogue: normalize, round, write g_A [B,S,E].
    const float inv0 = 1.0f / l0;
    const float inv1 = 1.0f / l1;
    const int row0 = q0 + rbase + g;
#pragma unroll
    for (int nt = 0; nt < 8; nt++) {
        int d = nt * 8 + 2 * tg;
        float* p0 = g_A + ((size_t)b * SS + row0    ) * EE + h * DKK + d;
        float* p1 = g_A + ((size_t)b * SS + row0 + 8) * EE + h * DKK + d;
        *(float2*)p0 = make_float2(f2tff(o[nt][0] * inv0), f2tff(o[nt][1] * inv0));
        *(float2*)p1 = make_float2(f2tff(o[nt][2] * inv1), f2tff(o[nt][3] * inv1));
    }
}

// ===========================================================================

extern "C" void kernel_launch(void* const* d_in, const int* in_sizes, int n_in,
                              void* d_out, int out_size)
{
    const float* x  = (const float*)d_in[0];
    const float* WQ = (const float*)d_in[1];
    const float* WK = (const float*)d_in[2];
    const float* WV = (const float*)d_in[3];
    const float* WO = (const float*)d_in[4];
    float* out = (float*)d_out;

    (void)in_sizes; (void)n_in; (void)out_size;

    // 0) Round X; transpose+round weights.
    xround_kernel<<<(MTOT * EE) / (256 * 4), 256>>>(x);
    wtrans_kernel<<<dim3(EE / 32, EE / 32, 4), dim3(32, 8)>>>(WQ, WK, WV, WO);

    // 1) QKV projections.
    cudaFuncSetAttribute(gemm_tc<0>,
                         cudaFuncAttributeMaxDynamicSharedMemorySize,
                         GEMM_SMEM_BYTES);
    gemm_tc<0><<<dim3(EE / 128, MTOT / 128, 3), 256, GEMM_SMEM_BYTES>>>(nullptr);

    // 2) Causal flash attention (128 q-rows/CTA, 2 CTAs per SM).
    cudaFuncSetAttribute(attn_tc,
                         cudaFuncAttributeMaxDynamicSharedMemorySize,
                         ATTN_SMEM_BYTES);
    attn_tc<<<dim3(SS / AQROWS, HH, BB), 256, ATTN_SMEM_BYTES>>>();

    // 3) Output projection.
    cudaFuncSetAttribute(gemm_tc<1>,
                         cudaFuncAttributeMaxDynamicSharedMemorySize,
                         GEMM_SMEM_BYTES);
    gemm_tc<1><<<dim3(EE / 128, MTOT / 128), 256, GEMM_SMEM_BYTES>>>(out);
}